// round 17
// baseline (speedup 1.0000x reference)
#include <cuda_runtime.h>
#include <cuda_fp16.h>

#define SS   1024
#define BB   8
#define NH   8
#define BH   (BB * NH)          // 64

// Scratch: attention out, fp16, ROW-FEATURE layout [b*1024+s][h*8+d]  (1 MB)
__device__ __half g_aoh[BB * SS * 64];

// attn smem: kh[1024][8] half (16KB), vt[8][1032] half (16.5KB)
#define SM_KH 0
#define SM_VT 16384
#define VT_STRIDE 1032              // word-stride 516 = 4 mod 32: bank-free b-frags
#define SMEM_BYTES (16384 + 8 * VT_STRIDE * 2)   // 32896

typedef unsigned long long u64;

__device__ __forceinline__ unsigned h2pk(float hi, float lo) {
    unsigned r; asm("cvt.rn.f16x2.f32 %0,%1,%2;" : "=r"(r) : "f"(hi), "f"(lo)); return r;
}
__device__ __forceinline__ unsigned hadd2(unsigned a, unsigned b) {
    unsigned r; asm("add.rn.f16x2 %0,%1,%2;" : "=r"(r) : "r"(a), "r"(b)); return r;
}
__device__ __forceinline__ float2 h2f2(unsigned v) {
    __half2 h = *(__half2*)&v;
    return __half22float2(h);
}
// ---- packed f32x2 (untyped .b64 -> "l" constraints; validated R3-R5) ----
__device__ __forceinline__ u64 pk2f(float lo, float hi) {
    u64 r; asm("mov.b64 %0,{%1,%2};" : "=l"(r) : "f"(lo), "f"(hi)); return r;
}
__device__ __forceinline__ void upk2(u64 v, float& lo, float& hi) {
    asm("mov.b64 {%0,%1},%2;" : "=f"(lo), "=f"(hi) : "l"(v));
}
__device__ __forceinline__ u64 fadd2(u64 a, u64 b) {
    u64 r; asm("add.rn.f32x2 %0,%1,%2;" : "=l"(r) : "l"(a), "l"(b)); return r;
}
__device__ __forceinline__ u64 ffma2(u64 a, u64 b, u64 c) {
    u64 r; asm("fma.rn.f32x2 %0,%1,%2,%3;" : "=l"(r) : "l"(a), "l"(b), "l"(c)); return r;
}
__device__ __forceinline__ u64 fmul2(u64 a, u64 b) {
    u64 r; asm("mul.rn.f32x2 %0,%1,%2;" : "=l"(r) : "l"(a), "l"(b)); return r;
}
__device__ __forceinline__ void mma_16x8x8(float& c0, float& c1, float& c2, float& c3,
                                           unsigned a0, unsigned a1, unsigned b0) {
    asm("mma.sync.aligned.m16n8k8.row.col.f32.f16.f16.f32 "
        "{%0,%1,%2,%3},{%4,%5},{%6},{%0,%1,%2,%3};"
        : "+f"(c0), "+f"(c1), "+f"(c2), "+f"(c3)
        : "r"(a0), "r"(a1), "r"(b0));
}
__device__ __forceinline__ void mma_16x8x16(float& c0, float& c1, float& c2, float& c3,
                                            unsigned a0, unsigned a1, unsigned a2, unsigned a3,
                                            unsigned b0, unsigned b1) {
    asm("mma.sync.aligned.m16n8k16.row.col.f32.f16.f16.f32 "
        "{%0,%1,%2,%3},{%4,%5,%6,%7},{%8,%9},{%0,%1,%2,%3};"
        : "+f"(c0), "+f"(c1), "+f"(c2), "+f"(c3)
        : "r"(a0), "r"(a1), "r"(a2), "r"(a3), "r"(b0), "r"(b1));
}

// MUFU-free packed exp2: DST = fp16x2( 2^X1 (hi), 2^X0 (lo) ).
// Magic-constant round-to-int, deg-4 Taylor for 2^f (|f|<=0.5, rel err ~4e-5),
// exponent scale via IMAD bit-trick. Runs on FMA/ALU pipes only.
// Uses in-scope constants MAG2/NMAG2/M1_2/C4_2/C3_2/C2_2/C1_2/ONE_2.
#define EXP2PK(DST, X0, X1) do {                                               \
    u64 s2_ = pk2f(X0, X1);                                                    \
    u64 z2_ = fadd2(s2_, MAG2);          /* n encoded in low mantissa */       \
    u64 n2_ = fadd2(z2_, NMAG2);         /* n = round(s) */                    \
    u64 f2_ = ffma2(n2_, M1_2, s2_);     /* f = s - n, |f|<=0.5 */             \
    u64 p2_ = ffma2(C4_2, f2_, C3_2);                                          \
    p2_ = ffma2(p2_, f2_, C2_2);                                               \
    p2_ = ffma2(p2_, f2_, C1_2);                                               \
    p2_ = ffma2(p2_, f2_, ONE_2);                                              \
    float zl_, zh_; upk2(z2_, zl_, zh_);                                       \
    unsigned il_ = __float_as_uint(zl_) * 0x800000u + 0x3F800000u;             \
    unsigned ih_ = __float_as_uint(zh_) * 0x800000u + 0x3F800000u;             \
    u64 sc_ = pk2f(__uint_as_float(il_), __uint_as_float(ih_));                \
    u64 r2_ = fmul2(p2_, sc_);                                                 \
    float rl_, rh_; upk2(r2_, rl_, rh_);                                       \
    DST = h2pk(rh_, rl_);                                                      \
} while (0)

// QK issue for one tile into score regs S (4 groups x 4)
#define QK_ISSUE(S, QA0, QA1, B0, B1, B2, B3)  do {                            \
    S##00=0.f;S##01=0.f;S##02=0.f;S##03=0.f;                                   \
    S##10=0.f;S##11=0.f;S##12=0.f;S##13=0.f;                                   \
    S##20=0.f;S##21=0.f;S##22=0.f;S##23=0.f;                                   \
    S##30=0.f;S##31=0.f;S##32=0.f;S##33=0.f;                                   \
    mma_16x8x8(S##00,S##01,S##02,S##03, QA0,QA1, B0);                          \
    mma_16x8x8(S##10,S##11,S##12,S##13, QA0,QA1, B1);                          \
    mma_16x8x8(S##20,S##21,S##22,S##23, QA0,QA1, B2);                          \
    mma_16x8x8(S##30,S##31,S##32,S##33, QA0,QA1, B3);                          \
} while (0)

// Consume scores S: MUFU-free exp2 -> L accumulate -> 2 PV mmas
#define CONSUME(S, L0, L1, OX0,OX1,OX2,OX3, OY0,OY1,OY2,OY3, VB0,VB1,VB2,VB3) do { \
    unsigned a00, a01, a10, a11, a20, a21, a30, a31;                           \
    EXP2PK(a00, S##00, S##01);                                                 \
    EXP2PK(a01, S##02, S##03);                                                 \
    EXP2PK(a10, S##10, S##11);                                                 \
    EXP2PK(a11, S##12, S##13);                                                 \
    EXP2PK(a20, S##20, S##21);                                                 \
    EXP2PK(a21, S##22, S##23);                                                 \
    EXP2PK(a30, S##30, S##31);                                                 \
    EXP2PK(a31, S##32, S##33);                                                 \
    unsigned T0 = hadd2(hadd2(a00, a10), hadd2(a20, a30));                     \
    unsigned T1 = hadd2(hadd2(a01, a11), hadd2(a21, a31));                     \
    float2 f0 = h2f2(T0);                                                      \
    float2 f1 = h2f2(T1);                                                      \
    L0 += f0.x + f0.y;                                                         \
    L1 += f1.x + f1.y;                                                         \
    mma_16x8x16(OX0,OX1,OX2,OX3, a00, a01, a10, a11, VB0, VB1);                \
    mma_16x8x16(OY0,OY1,OY2,OY3, a20, a21, a30, a31, VB2, VB3);                \
} while (0)

// ---------------------------------------------------------------------------
// Fused qlayer + flash-attention via mma.sync, cross-iteration pipelined,
// softmax exp on the FMA/ALU pipes (MUFU eliminated from the mainloop).
// Grid 256 = 64 heads x 4 (2 blocks/SM, ONE wave); 8 warps; each warp owns
// two 16-row tiles (r0, r0+128) sharing the key/value b-fragments.
// ---------------------------------------------------------------------------
__global__ __launch_bounds__(256, 2) void attn_kernel(const float* __restrict__ x,
                                                      const float* __restrict__ phi) {
    extern __shared__ char dynsmem[];
    __half*  kh = (__half*)(dynsmem + SM_KH);       // [j][8] row-major fp16
    __half*  vt = (__half*)(dynsmem + SM_VT);       // [d][VT_STRIDE] fp16
    const unsigned* khw = (const unsigned*)kh;      // half2 words: [j*4 + p]
    const unsigned* vtw = (const unsigned*)vt;      // [d*516 + j/2]

    const int blk = blockIdx.x;
    const int bh = blk >> 2;
    const int b = bh >> 3, h = bh & 7;
    const int tid = threadIdx.x;

    float ph0 = phi[0], ph1 = phi[1], ph2 = phi[2], ph3 = phi[3];
    float ph4 = phi[4], ph5 = phi[5], ph6 = phi[6], ph7 = phi[7];

    // ---- prologue: qlayer (prefix products of cos) -> kh and vt ----
    #pragma unroll
    for (int it = 0; it < 4; it++) {
        int s = tid + it * 256;
        const float4* xp = (const float4*)(x + ((size_t)((b << 10) + s) << 6) + (h << 3));
        float4 xa = xp[0];
        float4 xb = xp[1];
        float k0 = __cosf(xa.x + ph0);
        float c1 = __cosf(xa.y + ph1);
        float c2 = __cosf(xa.z + ph2);
        float c3 = __cosf(xa.w + ph3);
        float c4 = __cosf(xb.x + ph4);
        float c5 = __cosf(xb.y + ph5);
        float c6 = __cosf(xb.z + ph6);
        float c7 = __cosf(xb.w + ph7);
        float kv1 = k0 * c1;
        float kv2 = kv1 * c2;
        float kv3 = kv2 * c3;
        float kv4 = kv3 * c4;
        float kv5 = kv4 * c5;
        float kv6 = kv5 * c6;
        float kv7 = kv6 * c7;
        float t = c1 * c2;
        t *= c3; t *= c4; t *= c5; t *= c6; t *= c7;

        unsigned w0 = h2pk(kv1, t);
        unsigned w1 = h2pk(kv3, kv2);
        unsigned w2 = h2pk(kv5, kv4);
        unsigned w3 = h2pk(kv7, kv6);
        ((uint4*)kh)[s] = make_uint4(w0, w1, w2, w3);

        __half2 p0 = *(__half2*)&w0, p1 = *(__half2*)&w1;
        __half2 p2 = *(__half2*)&w2, p3 = *(__half2*)&w3;
        vt[0 * VT_STRIDE + s] = p0.x;
        vt[1 * VT_STRIDE + s] = p0.y;
        vt[2 * VT_STRIDE + s] = p1.x;
        vt[3 * VT_STRIDE + s] = p1.y;
        vt[4 * VT_STRIDE + s] = p2.x;
        vt[5 * VT_STRIDE + s] = p2.y;
        vt[6 * VT_STRIDE + s] = p3.x;
        vt[7 * VT_STRIDE + s] = p3.y;
    }
    __syncthreads();

    // ---- exp2 constants (FMA-pipe exp; hoisted to registers) ----
    const u64 MAG2  = pk2f(12582912.0f, 12582912.0f);    // 1.5 * 2^23
    const u64 NMAG2 = pk2f(-12582912.0f, -12582912.0f);
    const u64 M1_2  = pk2f(-1.0f, -1.0f);
    const u64 C4_2  = pk2f(0.00961813f, 0.00961813f);
    const u64 C3_2  = pk2f(0.05550411f, 0.05550411f);
    const u64 C2_2  = pk2f(0.24022651f, 0.24022651f);
    const u64 C1_2  = pk2f(0.69314718f, 0.69314718f);
    const u64 ONE_2 = pk2f(1.0f, 1.0f);

    // ---- per-warp Q fragments for BOTH tiles ----
    const int wid = tid >> 5, lane = tid & 31;
    const int r0A = ((blk & 3) << 8) + (wid << 4);
    const int r0B = r0A + 128;
    const int qr = lane >> 2, qm = lane & 3;
    const float SC = 0.35355339059327373f * 1.4426950408889634f;

    unsigned qA0, qA1, qB0, qB1;
    {
        float2 f;
        f = h2f2(khw[(r0A + qr) * 4 + qm]);      qA0 = h2pk(f.y * SC, f.x * SC);
        f = h2f2(khw[(r0A + qr + 8) * 4 + qm]);  qA1 = h2pk(f.y * SC, f.x * SC);
        f = h2f2(khw[(r0B + qr) * 4 + qm]);      qB0 = h2pk(f.y * SC, f.x * SC);
        f = h2f2(khw[(r0B + qr + 8) * 4 + qm]);  qB1 = h2pk(f.y * SC, f.x * SC);
    }

    // accumulators
    float oAX0=0.f,oAX1=0.f,oAX2=0.f,oAX3=0.f, oAY0=0.f,oAY1=0.f,oAY2=0.f,oAY3=0.f;
    float oBX0=0.f,oBX1=0.f,oBX2=0.f,oBX3=0.f, oBY0=0.f,oBY1=0.f,oBY2=0.f,oBY3=0.f;
    float lA0=0.f, lA1=0.f, lB0=0.f, lB1=0.f;

    const int vbase = (lane >> 2) * (VT_STRIDE / 2) + (lane & 3);

    // scores (single buffer per tile: reissued only after consumption)
    float sA00,sA01,sA02,sA03, sA10,sA11,sA12,sA13;
    float sA20,sA21,sA22,sA23, sA30,sA31,sA32,sA33;
    float sB00,sB01,sB02,sB03, sB10,sB11,sB12,sB13;
    float sB20,sB21,sB22,sB23, sB30,sB31,sB32,sB33;

    // current b-frags (keys + values) for chunk c
    unsigned cb0 = khw[0 * 4 + lane];
    unsigned cb1 = khw[8 * 4 + lane];
    unsigned cb2 = khw[16 * 4 + lane];
    unsigned cb3 = khw[24 * 4 + lane];
    unsigned cv0 = vtw[vbase];
    unsigned cv1 = vtw[vbase + 4];
    unsigned cv2 = vtw[vbase + 8];
    unsigned cv3 = vtw[vbase + 12];

    // pipeline prologue: issue QK for chunk 0, both tiles
    QK_ISSUE(sA, qA0, qA1, cb0, cb1, cb2, cb3);
    QK_ISSUE(sB, qB0, qB1, cb0, cb1, cb2, cb3);

    for (int c = 0; c < SS - 32; c += 32) {
        int n = c + 32;
        unsigned nb0 = khw[(n +  0) * 4 + lane];
        unsigned nb1 = khw[(n +  8) * 4 + lane];
        unsigned nb2 = khw[(n + 16) * 4 + lane];
        unsigned nb3 = khw[(n + 24) * 4 + lane];
        unsigned nv0 = vtw[vbase + (n >> 1)];
        unsigned nv1 = vtw[vbase + (n >> 1) + 4];
        unsigned nv2 = vtw[vbase + (n >> 1) + 8];
        unsigned nv3 = vtw[vbase + (n >> 1) + 12];

        CONSUME(sA, lA0, lA1, oAX0,oAX1,oAX2,oAX3, oAY0,oAY1,oAY2,oAY3,
                cv0, cv1, cv2, cv3);
        QK_ISSUE(sA, qA0, qA1, nb0, nb1, nb2, nb3);

        CONSUME(sB, lB0, lB1, oBX0,oBX1,oBX2,oBX3, oBY0,oBY1,oBY2,oBY3,
                cv0, cv1, cv2, cv3);
        QK_ISSUE(sB, qB0, qB1, nb0, nb1, nb2, nb3);

        cv0 = nv0; cv1 = nv1; cv2 = nv2; cv3 = nv3;
        cb0 = nb0; cb1 = nb1; cb2 = nb2; cb3 = nb3;
    }

    // pipeline epilogue: consume final chunk
    CONSUME(sA, lA0, lA1, oAX0,oAX1,oAX2,oAX3, oAY0,oAY1,oAY2,oAY3,
            cv0, cv1, cv2, cv3);
    CONSUME(sB, lB0, lB1, oBX0,oBX1,oBX2,oBX3, oBY0,oBY1,oBY2,oBY3,
            cv0, cv1, cv2, cv3);

    // ---- reduce L across quads, write both tiles ----
    lA0 += __shfl_xor_sync(0xffffffffu, lA0, 1);
    lA0 += __shfl_xor_sync(0xffffffffu, lA0, 2);
    lA1 += __shfl_xor_sync(0xffffffffu, lA1, 1);
    lA1 += __shfl_xor_sync(0xffffffffu, lA1, 2);
    lB0 += __shfl_xor_sync(0xffffffffu, lB0, 1);
    lB0 += __shfl_xor_sync(0xffffffffu, lB0, 2);
    lB1 += __shfl_xor_sync(0xffffffffu, lB1, 1);
    lB1 += __shfl_xor_sync(0xffffffffu, lB1, 2);

    unsigned* aoh = (unsigned*)g_aoh;
    {
        float inv0 = 1.f / lA0, inv1 = 1.f / lA1;
        float o0 = oAX0 + oAY0, o1 = oAX1 + oAY1, o2 = oAX2 + oAY2, o3 = oAX3 + oAY3;
        int roww = (((b << 10) + r0A + qr) << 5) + (h << 2) + qm;
        aoh[roww]       = h2pk(o1 * inv0, o0 * inv0);
        aoh[roww + 256] = h2pk(o3 * inv1, o2 * inv1);
    }
    {
        float inv0 = 1.f / lB0, inv1 = 1.f / lB1;
        float o0 = oBX0 + oBY0, o1 = oBX1 + oBY1, o2 = oBX2 + oBY2, o3 = oBX3 + oBY3;
        int roww = (((b << 10) + r0B + qr) << 5) + (h << 2) + qm;
        aoh[roww]       = h2pk(o1 * inv0, o0 * inv0);
        aoh[roww + 256] = h2pk(o3 * inv1, o2 * inv1);
    }
}

// ---------------------------------------------------------------------------
// Tensor-core epilogue (unchanged): out = ao @ W^T + bias.
// ---------------------------------------------------------------------------
__global__ __launch_bounds__(256) void epilogue_kernel(const float* __restrict__ W,
                                                       const float* __restrict__ bias,
                                                       float* __restrict__ out) {
    __shared__ __align__(16) __half sA[32 * 64];    // 4 KB

    const int tid = threadIdx.x;
    const int row0 = blockIdx.x * 32;

    {
        const uint4* src = (const uint4*)((const __half*)g_aoh + (size_t)row0 * 64);
        int off = tid * 16;
        int sw = off ^ (((off >> 7) & 7) << 4);
        *(uint4*)((char*)sA + sw) = src[tid];
    }
    __syncthreads();

    const int w = tid >> 5, lane = tid & 31;
    const int mt = w & 1;
    const int ntb = (w >> 1) << 1;
    unsigned sbase = (unsigned)__cvta_generic_to_shared(sA);

    unsigned a0[4], a1[4], a2[4], a3[4];
    #pragma unroll
    for (int kc = 0; kc < 4; kc++) {
        int r = mt * 16 + (lane & 15);
        int cb = ((lane >> 4) << 4) + (kc << 5);
        int boff = r * 128 + cb;
        int bsw = boff ^ (((boff >> 7) & 7) << 4);
        asm("ldmatrix.sync.aligned.m8n8.x4.shared.b16 {%0,%1,%2,%3},[%4];"
            : "=r"(a0[kc]), "=r"(a1[kc]), "=r"(a2[kc]), "=r"(a3[kc])
            : "r"(sbase + bsw));
    }

    const int m = lane & 3;
    float cE0=0.f,cE1=0.f,cE2=0.f,cE3=0.f, cO0=0.f,cO1=0.f,cO2=0.f,cO3=0.f;
    float dE0=0.f,dE1=0.f,dE2=0.f,dE3=0.f, dO0=0.f,dO1=0.f,dO2=0.f,dO3=0.f;

    #pragma unroll
    for (int t = 0; t < 2; t++) {
        int nt = ntb + t;
        const float* wr = W + (nt * 8 + (lane >> 2)) * 64;
        #pragma unroll
        for (int kc = 0; kc < 4; kc++) {
            float2 wA = *(const float2*)(wr + kc * 16 + 2 * m);
            float2 wB = *(const float2*)(wr + kc * 16 + 2 * m + 8);
            float hAx = __half2float(__float2half_rn(wA.x));
            float hAy = __half2float(__float2half_rn(wA.y));
            float hBx = __half2float(__float2half_rn(wB.x));
            float hBy = __half2float(__float2half_rn(wB.y));
            unsigned bh0 = h2pk(hAy, hAx);
            unsigned bh1 = h2pk(hBy, hBx);
            unsigned bl0 = h2pk(wA.y - hAy, wA.x - hAx);
            unsigned bl1 = h2pk(wB.y - hBy, wB.x - hBx);
            if (t == 0) {
                if (kc & 1) {
                    mma_16x8x16(cO0,cO1,cO2,cO3, a0[kc],a1[kc],a2[kc],a3[kc], bh0, bh1);
                    mma_16x8x16(cO0,cO1,cO2,cO3, a0[kc],a1[kc],a2[kc],a3[kc], bl0, bl1);
                } else {
                    mma_16x8x16(cE0,cE1,cE2,cE3, a0[kc],a1[kc],a2[kc],a3[kc], bh0, bh1);
                    mma_16x8x16(cE0,cE1,cE2,cE3, a0[kc],a1[kc],a2[kc],a3[kc], bl0, bl1);
                }
            } else {
                if (kc & 1) {
                    mma_16x8x16(dO0,dO1,dO2,dO3, a0[kc],a1[kc],a2[kc],a3[kc], bh0, bh1);
                    mma_16x8x16(dO0,dO1,dO2,dO3, a0[kc],a1[kc],a2[kc],a3[kc], bl0, bl1);
                } else {
                    mma_16x8x16(dE0,dE1,dE2,dE3, a0[kc],a1[kc],a2[kc],a3[kc], bh0, bh1);
                    mma_16x8x16(dE0,dE1,dE2,dE3, a0[kc],a1[kc],a2[kc],a3[kc], bl0, bl1);
                }
            }
        }
    }

    {
        int r = row0 + mt * 16 + (lane >> 2);
        int e0 = ntb * 8 + 2 * m;
        float2 bb0 = *(const float2*)(bias + e0);
        float2 bb1 = *(const float2*)(bias + e0 + 8);
        *(float2*)(out + (size_t)r * 64 + e0)
            = make_float2(cE0 + cO0 + bb0.x, cE1 + cO1 + bb0.y);
        *(float2*)(out + (size_t)(r + 8) * 64 + e0)
            = make_float2(cE2 + cO2 + bb0.x, cE3 + cO3 + bb0.y);
        *(float2*)(out + (size_t)r * 64 + e0 + 8)
            = make_float2(dE0 + dO0 + bb1.x, dE1 + dO1 + bb1.y);
        *(float2*)(out + (size_t)(r + 8) * 64 + e0 + 8)
            = make_float2(dE2 + dO2 + bb1.x, dE3 + dO3 + bb1.y);
    }
}

// ---------------------------------------------------------------------------
extern "C" void kernel_launch(void* const* d_in, const int* in_sizes, int n_in,
                              void* d_out, int out_size) {
    const float* x    = (const float*)d_in[0];
    const float* phi  = (const float*)d_in[1];
    const float* W    = (const float*)d_in[2];
    const float* bias = (const float*)d_in[3];
    float* out = (float*)d_out;

    cudaFuncSetAttribute(attn_kernel, cudaFuncAttributeMaxDynamicSharedMemorySize,
                         SMEM_BYTES);
    attn_kernel<<<BH * 4, 256, SMEM_BYTES>>>(x, phi);
    epilogue_kernel<<<(BB * SS) / 32, 256>>>(W, bias, out);
}